// round 17
// baseline (speedup 1.0000x reference)
#include <cuda_runtime.h>
#include <cstdint>

#define BB 256
#define TT 2048
#define II 64
#define HH 256

// Persistent scratch for the input projection (zero-init; t>=len never written).
__device__ float g_xp[(size_t)BB * TT * HH];

typedef unsigned long long u64;

__device__ __forceinline__ u64 pack2(float lo, float hi) {
    u64 r; asm("mov.b64 %0, {%1,%2};" : "=l"(r) : "f"(lo), "f"(hi)); return r;
}
__device__ __forceinline__ void ffma2(u64& acc, u64 a, u64 b) {
    asm("fma.rn.f32x2 %0, %1, %2, %0;" : "+l"(acc) : "l"(a), "l"(b));
}
__device__ __forceinline__ u64 add2(u64 a, u64 b) {
    u64 r; asm("add.rn.f32x2 %0, %1, %2;" : "=l"(r) : "l"(a), "l"(b)); return r;
}
__device__ __forceinline__ float2 unpack2(u64 v) {
    float2 f; asm("mov.b64 {%0,%1}, %2;" : "=f"(f.x), "=f"(f.y) : "l"(v)); return f;
}
__device__ __forceinline__ float tanhap(float x) {
    float y; asm("tanh.approx.f32 %0, %1;" : "=f"(y) : "f"(x)); return y;
}
__device__ __forceinline__ u64 shfl64(u64 v, int mask) {
    return __shfl_xor_sync(0xffffffffu, v, mask);
}

// ---------------------------------------------------------------------------
// Kernel A: xp[b,t,h] = sum_i x[b,t,i]*W_ih[h,i] + b_ih[h] + b_hh[h], t < len[b]
// ---------------------------------------------------------------------------
__global__ __launch_bounds__(256) void xproj_kernel(
    const float* __restrict__ x,
    const int*   __restrict__ lengths,
    const float* __restrict__ W_ih,
    const float* __restrict__ b_ih,
    const float* __restrict__ b_hh)
{
    extern __shared__ float sm[];
    float* ws = sm;                 // [256][65]
    float* xs = sm + 256 * 65;      // [64][64]

    const int b  = blockIdx.y;
    const int t0 = blockIdx.x * 64;
    const int len = lengths[b];
    if (t0 >= len) return;
    const int tcnt = min(64, len - t0);
    const int tid = threadIdx.x;

    for (int idx = tid; idx < HH * II; idx += 256) {
        int h = idx >> 6, i = idx & 63;
        ws[h * 65 + i] = W_ih[idx];
    }
    const float* xbase = x + ((size_t)b * TT + t0) * II;
    for (int idx = tid; idx < tcnt * II; idx += 256) {
        xs[idx] = xbase[idx];
    }
    __syncthreads();

    const int h = tid;
    u64 wp[II / 2];
#pragma unroll
    for (int q = 0; q < II / 2; q++)
        wp[q] = pack2(ws[h * 65 + 2 * q], ws[h * 65 + 2 * q + 1]);
    const u64 bias0 = pack2(b_ih[h] + b_hh[h], 0.f);

    float* xpb = g_xp + ((size_t)b * TT + t0) * HH + h;

    for (int tt = 0; tt < tcnt; tt++) {
        u64 acc0 = bias0, acc1 = 0ull;
        const ulonglong2* xr = (const ulonglong2*)(xs + tt * II);
#pragma unroll
        for (int q = 0; q < II / 4; q++) {
            ulonglong2 xv = xr[q];
            ffma2(acc0, wp[2 * q],     xv.x);
            ffma2(acc1, wp[2 * q + 1], xv.y);
        }
        float2 f0 = unpack2(acc0), f1 = unpack2(acc1);
        xpb[(size_t)tt * HH] = (f0.x + f0.y) + (f1.x + f1.y);
    }
}

// ---------------------------------------------------------------------------
// Kernel B: persistent scan, 512 threads/CTA (4 warps/SMSP for latency
// overlap), k-split 16, 8-j groups.
// 128 CTAs, 2 batch rows/CTA. Thread: c = tid&15 (k ≡ c mod 16),
// G = tid>>4 (0..31) owns j in [8G, 8G+8).
// Acc slots: X[s] = Σ (W[8G+2s][k]·h0, W[8G+2s+1][k]·h1), Y[s] with (h1,h0).
// k-iters 0..8: W in regs (36 u64 = 72 regs, fits the 128-reg/thread cap).
// k-iters 9..15: W from smem rows k>=144 via 2x LDS.128 (RS=260: starts
// 4c+8G mod 32 tile the banks 4-ways -> conflict-free).
// Reduce: levels 8/4/2 keep/send, level 1 allreduce -> lane c owns scalar
// (j_out = 8G + 2s* + q, batch bsh = q ^ (c>>3)), s* = ((c>>2)&1)*2 + ((c>>1)&1).
// ---------------------------------------------------------------------------
#define RS  260
#define K0  144
#define RKI 9
#define WROWS (HH - K0)          // 112 smem W rows

__global__ __launch_bounds__(512, 1) void scan_kernel(
    const float* __restrict__ W_hh,
    const int*   __restrict__ lengths,
    const float* __restrict__ W_fc,
    const float* __restrict__ b_fc,
    float*       __restrict__ out)
{
    extern __shared__ float sm[];
    float*  Wsm  = sm;                               // [112][260]
    float2* hb0  = (float2*)(sm + WROWS * RS);       // [256] (h_b0, h_b1)
    float2* hb1  = hb0 + HH;                         // [256]
    float*  hlast = (float*)(hb1 + HH);              // [2][256]
    float*  red   = hlast + 2 * HH;                  // [16]

    const int tid = threadIdx.x;
    const int c   = tid & 15;
    const int G   = tid >> 4;            // 0..31, j-group
    const int jg  = 8 * G;
    const int b0  = 2 * blockIdx.x;
    const int L0 = lengths[b0], L1 = lengths[b0 + 1];
    const int Tmax = max(L0, L1);

    // Stage W^T rows k >= K0 into smem (coalesced read of W_hh).
    for (int idx = tid; idx < HH * HH; idx += 512) {
        int j = idx >> 8, k = idx & 255;
        float v = W_hh[idx];
        if (k >= K0) Wsm[(k - K0) * RS + j] = v;
    }
    // Register W for k-iters 0..RKI-1: wr[i][s] = (W[jg+2s][k], W[jg+2s+1][k]).
    u64 wr[RKI][4];
#pragma unroll
    for (int i = 0; i < RKI; i++) {
        int k = 16 * i + c;
#pragma unroll
        for (int s = 0; s < 4; s++) {
            int jj = jg + 2 * s;
            wr[i][s] = pack2(__ldg(&W_hh[jj * HH + k]),
                             __ldg(&W_hh[(jj + 1) * HH + k]));
        }
    }
    if (tid < HH) {
        hb0[tid] = make_float2(0.f, 0.f);
        hlast[tid] = 0.f; hlast[HH + tid] = 0.f;
    }
    __syncthreads();

    // Per-lane tail mapping.
    const int sstar = ((c >> 2) & 1) * 2 + ((c >> 1) & 1);
    const int q     = c & 1;
    const int typeY = (c >> 3) & 1;
    const int j_out = jg + 2 * sstar + q;
    const int bsh   = q ^ typeY;                 // 0 -> batch b0, 1 -> b0+1
    const int Lme   = bsh ? L1 : L0;
    const float* px = g_xp + (size_t)(b0 + bsh) * TT * HH + j_out;

    float e = px[0];

    for (int t = 0; t < Tmax; t++) {
        const float2* hc = (t & 1) ? hb1 : hb0;
        float2*       hn = (t & 1) ? hb0 : hb1;

        int tn = min(t + 1, Tmax - 1);
        float en = px[(size_t)tn * HH];

        u64 X[4], Y[4];
#pragma unroll
        for (int s = 0; s < 4; s++) { X[s] = 0ull; Y[s] = 0ull; }

#pragma unroll
        for (int i = 0; i < RKI; i++) {
            float2 hvf = hc[16 * i + c];
            u64 hv = pack2(hvf.x, hvf.y);
            u64 hs = pack2(hvf.y, hvf.x);
#pragma unroll
            for (int s = 0; s < 4; s++) {
                ffma2(X[s], wr[i][s], hv);
                ffma2(Y[s], wr[i][s], hs);
            }
        }
#pragma unroll
        for (int i = RKI; i < 16; i++) {
            float2 hvf = hc[16 * i + c];
            u64 hv = pack2(hvf.x, hvf.y);
            u64 hs = pack2(hvf.y, hvf.x);
            const float* wb = Wsm + (16 * (i - RKI) + c) * RS + jg;
            ulonglong2 wa = *(const ulonglong2*)(wb);       // j 0..3 of group
            ulonglong2 wbv = *(const ulonglong2*)(wb + 4);  // j 4..7
            ffma2(X[0], wa.x,  hv); ffma2(X[1], wa.y,  hv);
            ffma2(X[2], wbv.x, hv); ffma2(X[3], wbv.y, hv);
            ffma2(Y[0], wa.x,  hs); ffma2(Y[1], wa.y,  hs);
            ffma2(Y[2], wbv.x, hs); ffma2(Y[3], wbv.y, hs);
        }

        // Reduce-scatter over 16 k-lanes.
        // Level mask 8: pick X vs Y type.
        u64 Z[4];
#pragma unroll
        for (int s = 0; s < 4; s++) {
            u64 keep = typeY ? Y[s] : X[s];
            u64 send = typeY ? X[s] : Y[s];
            Z[s] = add2(keep, shfl64(send, 8));
        }
        // Level mask 4: slots {0,1} vs {2,3}.
        const bool h2b = (c & 4) != 0;
        u64 U0, U1;
        {
            u64 k0 = h2b ? Z[2] : Z[0], s0 = h2b ? Z[0] : Z[2];
            U0 = add2(k0, shfl64(s0, 4));
            u64 k1 = h2b ? Z[3] : Z[1], s1 = h2b ? Z[1] : Z[3];
            U1 = add2(k1, shfl64(s1, 4));
        }
        // Level mask 2: slot 0 vs 1.
        const bool h1b = (c & 2) != 0;
        u64 F;
        {
            u64 kf = h1b ? U1 : U0, sf = h1b ? U0 : U1;
            F = add2(kf, shfl64(sf, 2));
        }
        // Level mask 1: allreduce pair (both lanes get identical full sum).
        F = add2(F, shfl64(F, 1));

        float2 f = unpack2(F);
        float fsel = q ? f.y : f.x;
        float v = tanhap(fsel + e);          // h_{b0+bsh}[j_out]

        // Batch-partner exchange (c^8: same j_out, other batch).
        float recv = __shfl_xor_sync(0xffffffffu, v, 8);
        if (bsh == 0) hn[j_out] = make_float2(v, recv);

        if (t == Lme - 1) hlast[bsh * HH + j_out] = v;

        e = en;
        __syncthreads();   // hn visible; fences next-iter writes vs reads
    }

    // Final FC: out[b] = dot(hlast[b], W_fc) + b_fc  (first 256 threads)
    if (tid < 256) {
        float wf = W_fc[tid];
#pragma unroll
        for (int bb = 0; bb < 2; bb++) {
            float v = hlast[bb * HH + tid] * wf;
#pragma unroll
            for (int o = 16; o > 0; o >>= 1) v += __shfl_down_sync(0xffffffffu, v, o);
            if ((tid & 31) == 0) red[bb * 8 + (tid >> 5)] = v;
        }
    }
    __syncthreads();
    if (tid < 2) {
        float s = b_fc[0];
#pragma unroll
        for (int w = 0; w < 8; w++) s += red[tid * 8 + w];
        out[b0 + tid] = s;
    }
}

// ---------------------------------------------------------------------------
extern "C" void kernel_launch(void* const* d_in, const int* in_sizes, int n_in,
                              void* d_out, int out_size)
{
    const float* x     = (const float*)d_in[0];
    const int*   lens  = (const int*)  d_in[1];
    const float* W_ih  = (const float*)d_in[2];
    const float* W_hh  = (const float*)d_in[3];
    const float* b_ih  = (const float*)d_in[4];
    const float* b_hh  = (const float*)d_in[5];
    const float* W_fc  = (const float*)d_in[6];
    const float* b_fc  = (const float*)d_in[7];
    float* out = (float*)d_out;

    const int A_SMEM = (256 * 65 + 64 * 64) * 4;                           // 82944 B
    const int B_SMEM = (WROWS * RS + 2 * HH * 2 + 2 * HH + 16) * 4;        // 122688 B
    cudaFuncSetAttribute(xproj_kernel, cudaFuncAttributeMaxDynamicSharedMemorySize, A_SMEM);
    cudaFuncSetAttribute(scan_kernel,  cudaFuncAttributeMaxDynamicSharedMemorySize, B_SMEM);

    dim3 gA(TT / 64, BB);
    xproj_kernel<<<gA, 256, A_SMEM>>>(x, lens, W_ih, b_ih, b_hh);
    scan_kernel<<<BB / 2, 512, B_SMEM>>>(W_hh, lens, W_fc, b_fc, out);
}